// round 15
// baseline (speedup 1.0000x reference)
#include <cuda_runtime.h>
#include <cuda_fp16.h>
#include <cstdint>

#define NN   2048
#define BB   32
#define II   32
#define OO   32
#define SS   12
#define EE   16
#define KK   3          // K+1 hops
#define BIS  12288      // B*II*SS
#define PW   (KK*II*OO)

// ---------------- scratch (device globals) ----------------------------------
__device__ float g_h1[II * NN];
__device__ float g_h2[II * EE];
__device__ float g_m[EE * EE];
__device__ float g_W[(size_t)NN * PW];
__device__ float g_bias[NN * OO];
// fp16 operands / results
__device__ __align__(16) __half g_Ah[(size_t)NN * NN];    // S        [n][k]
__device__ __align__(16) __half g_B0h[(size_t)BIS * NN];  // X^T      [col][k]
__device__ __align__(16) __half g_B1h[(size_t)BIS * NN];  // Y1^T     [col][k]
__device__ __align__(16) __half g_Y1h[(size_t)NN * BIS];  // Y1       [n][col]
__device__ __align__(16) __half g_Y2h[(size_t)NN * BIS];  // Y2       [n][col]

// ---------------- helpers ----------------------------------------------------
__device__ __forceinline__ uint32_t smem_u32(const void* p) {
    uint32_t a;
    asm("{ .reg .u64 t; cvta.to.shared.u64 t, %1; cvt.u32.u64 %0, t; }" : "=r"(a) : "l"(p));
    return a;
}
__device__ __forceinline__ void cp16(uint32_t dst, const void* src) {
    asm volatile("cp.async.cg.shared.global [%0], [%1], 16;" :: "r"(dst), "l"(src) : "memory");
}
#define CP_COMMIT() asm volatile("cp.async.commit_group;" ::: "memory")
#define CP_WAIT2()  asm volatile("cp.async.wait_group 2;" ::: "memory")
#define CP_WAIT0()  asm volatile("cp.async.wait_group 0;" ::: "memory")

__device__ __forceinline__ void ldsm4(uint32_t* r, uint32_t addr) {
    asm volatile("ldmatrix.sync.aligned.m8n8.x4.shared.b16 {%0,%1,%2,%3}, [%4];"
                 : "=r"(r[0]), "=r"(r[1]), "=r"(r[2]), "=r"(r[3]) : "r"(addr));
}
__device__ __forceinline__ void mma16816(float* c, const uint32_t* a, const uint32_t* b) {
    asm volatile(
        "mma.sync.aligned.m16n8k16.row.col.f32.f16.f16.f32 "
        "{%0,%1,%2,%3}, {%4,%5,%6,%7}, {%8,%9}, {%0,%1,%2,%3};"
        : "+f"(c[0]), "+f"(c[1]), "+f"(c[2]), "+f"(c[3])
        : "r"(a[0]), "r"(a[1]), "r"(a[2]), "r"(a[3]), "r"(b[0]), "r"(b[1]));
}
// packed fp32x2 FMA (base Blackwell PTX; per-lane IEEE fma)
__device__ __forceinline__ void ffma2(unsigned long long& c,
                                      unsigned long long a, unsigned long long b) {
    asm("fma.rn.f32x2 %0, %1, %2, %0;" : "+l"(c) : "l"(a), "l"(b));
}
__device__ __forceinline__ unsigned long long pk2(float lo, float hi) {
    unsigned long long r;
    asm("mov.b64 %0, {%1, %2};" : "=l"(r) : "f"(lo), "f"(hi));
    return r;
}
__device__ __forceinline__ void upk2(float& lo, float& hi, unsigned long long v) {
    asm("mov.b64 {%0, %1}, %2;" : "=f"(lo), "=f"(hi) : "l"(v));
}

// ---------------- 1. h1 -----------------------------------------------------
__global__ void k_h1(const float* __restrict__ x,
                     const float* __restrict__ fc0w,
                     const float* __restrict__ fc0b) {
    int idx = blockIdx.x * 256 + threadIdx.x;
    float acc = fc0b[0];
    const float* xr = x + (size_t)idx * SS;
#pragma unroll
    for (int s = 0; s < SS; ++s) acc = fmaf(xr[s], fc0w[s], acc);
    g_h1[idx] = tanhf(acc);
}

// ---------------- 2. h2 -----------------------------------------------------
__global__ void k_h2(const float* __restrict__ fc1w,
                     const float* __restrict__ fc1b) {
    int i = blockIdx.x >> 4;
    int d = blockIdx.x & 15;
    int tid = threadIdx.x;
    float p = 0.f;
    for (int n = tid; n < NN; n += 256)
        p = fmaf(g_h1[i * NN + n], fc1w[d * NN + n], p);
    __shared__ float red[256];
    red[tid] = p; __syncthreads();
    for (int st = 128; st > 0; st >>= 1) {
        if (tid < st) red[tid] += red[tid + st];
        __syncthreads();
    }
    if (tid == 0) g_h2[i * EE + d] = tanhf(red[0] + fc1b[d]);
}

// ---------------- 3. m ------------------------------------------------------
__global__ void k_m(const float* __restrict__ fc2w,
                    const float* __restrict__ fc2b) {
    int t = threadIdx.x;
    int d = t >> 4, e = t & 15;
    float acc = fc2b[e];
#pragma unroll
    for (int i = 0; i < II; ++i) acc = fmaf(g_h2[i * EE + d], fc2w[e * II + i], acc);
    g_m[d * EE + e] = tanhf(acc);
}

// ------- 4. adjacency softmax -> fp16 (16 rows/block, E2 tiled in smem) -----
// dyn smem: buf[16][NN] | E2s[256][17] | p[16][16]
#define ADJ_TS 256
#define ADJ_SMEM ((16 * NN + ADJ_TS * 17 + 256) * 4)
__global__ __launch_bounds__(256) void k_adj(const float* __restrict__ E1,
                                             const float* __restrict__ E2) {
    extern __shared__ float asmem[];
    float* buf = asmem;                        // 16*NN
    float* E2s = asmem + 16 * NN;              // 256*17
    float* p   = E2s + ADJ_TS * 17;            // 16*16
    int tid = threadIdx.x;
    int n0 = blockIdx.x * 16;

    {
        int r = tid >> 4, e = tid & 15;
        float a = 0.f;
#pragma unroll
        for (int d = 0; d < EE; ++d)
            a = fmaf(E1[(n0 + r) * EE + d], g_m[d * EE + e], a);
        p[tid] = a;
    }
    __syncthreads();
    const int r = tid >> 4, mloc = tid & 15;
    float pl[EE];
#pragma unroll
    for (int e = 0; e < EE; ++e) pl[e] = p[r * 16 + e];

    float lmax = 0.f;   // relu => logits >= 0
    for (int mt = 0; mt < NN; mt += ADJ_TS) {
        __syncthreads();
#pragma unroll
        for (int j = 0; j < 16; ++j) {
            int idx = tid + j * 256;          // 4096 scalars
            int mc = idx >> 4, e = idx & 15;
            E2s[mc * 17 + e] = E2[(size_t)(mt + mc) * EE + e];
        }
        __syncthreads();
#pragma unroll
        for (int j = 0; j < ADJ_TS / 16; ++j) {
            int mc = mloc + j * 16;
            const float* er = E2s + mc * 17;
            float a = 0.f;
#pragma unroll
            for (int e = 0; e < EE; ++e) a = fmaf(pl[e], er[e], a);
            a = fmaxf(a, 0.f);
            buf[r * NN + mt + mc] = a;
            lmax = fmaxf(lmax, a);
        }
    }
#pragma unroll
    for (int o = 8; o; o >>= 1) lmax = fmaxf(lmax, __shfl_xor_sync(0xffffffffu, lmax, o));

    float lsum = 0.f;
#pragma unroll
    for (int j = 0; j < NN / 16; ++j) {
        int mc = mloc + j * 16;
        float v = __expf(buf[r * NN + mc] - lmax);
        buf[r * NN + mc] = v;
        lsum += v;
    }
#pragma unroll
    for (int o = 8; o; o >>= 1) lsum += __shfl_xor_sync(0xffffffffu, lsum, o);
    float inv = 1.0f / lsum;

#pragma unroll
    for (int j = 0; j < NN / 16; ++j) {
        int mc = mloc + j * 16;
        g_Ah[(size_t)(n0 + r) * NN + mc] = __float2half_rn(buf[r * NN + mc] * inv);
    }
}

// --------- 5. B0h = fp16(x^T):  B0[(b,i,s)][m] = x[b,i,m,s] ----------------
__global__ __launch_bounds__(256) void k_split0(const float* __restrict__ x) {
    int bi = blockIdx.x;
    int m = blockIdx.y * 256 + threadIdx.x;
    const float* src = x + ((size_t)bi * NN + m) * SS;
    float v[SS];
#pragma unroll
    for (int s = 0; s < SS; ++s) v[s] = src[s];
#pragma unroll
    for (int s = 0; s < SS; ++s)
        g_B0h[(size_t)(bi * SS + s) * NN + m] = __float2half_rn(v[s]);
}

// ============== GEMM core defs ==============================================
// BM=128, BN=192, BK=64; warp tile 64x48 (8 warps = 2m x 4n); grid 16x64=1024
#define ROWB 144
#define MATSZ_A (128 * ROWB)    // 18432
#define MATSZ_B (192 * ROWB)    // 27648
#define STG   (MATSZ_A + MATSZ_B)   // 46080
#define NSTG  4
#define SMTOT (NSTG * STG)      // 184320
#define NCHUNK (NN / 64)        // 32
#define ROWP 132                // fp16 transpose-staging row pitch

// common GEMM body: computes acc for one 128x192 tile of C = Ah @ B^T
#define GEMM_BODY(pB)                                                           \
    const char* pAh = (const char*)g_Ah;                                        \
    const char* pBh = (const char*)(pB);                                        \
    const int m0 = blockIdx.x * 128;                                            \
    const int c0 = blockIdx.y * 192;                                            \
    auto load_stage = [&](int stg, int chunk) {                                 \
        const uint32_t base = sb + stg * STG;                                   \
        const int k0 = chunk * 64;                                              \
        _Pragma("unroll")                                                       \
        for (int r = 0; r < 10; ++r) {                                          \
            int id = tid + r * 256;                                             \
            if (id < 1024) {                                                    \
                int row = id >> 3, cc = id & 7;                                 \
                cp16(base + row * ROWB + cc * 16,                               \
                     pAh + ((size_t)(m0 + row) * NN + k0 + cc * 8) * 2);        \
            } else {                                                            \
                int idx = id - 1024;                                            \
                int row = idx >> 3, cc = idx & 7;                               \
                cp16(base + MATSZ_A + row * ROWB + cc * 16,                     \
                     pBh + ((size_t)(c0 + row) * NN + k0 + cc * 8) * 2);        \
            }                                                                   \
        }                                                                       \
    };                                                                          \
    float acc[4][6][4];                                                         \
    _Pragma("unroll")                                                           \
    for (int i = 0; i < 4; ++i)                                                 \
        _Pragma("unroll")                                                       \
        for (int j = 0; j < 6; ++j)                                             \
            _Pragma("unroll")                                                   \
            for (int q = 0; q < 4; ++q) acc[i][j][q] = 0.f;                     \
    load_stage(0, 0); CP_COMMIT();                                              \
    load_stage(1, 1); CP_COMMIT();                                              \
    load_stage(2, 2); CP_COMMIT();                                              \
    const int grp = lane >> 3, lr = lane & 7;                                   \
    const int a_row_base = m_off + (grp & 1) * 8 + lr;                          \
    const int a_kc = grp >> 1;                                                  \
    const int b_row_base = n_off + (grp >> 1) * 8 + lr;                         \
    const int b_kc = grp & 1;                                                   \
    for (int c = 0; c < NCHUNK; ++c) {                                          \
        const int st = c & 3;                                                   \
        if (c + 1 < NCHUNK) CP_WAIT2(); else CP_WAIT0();                        \
        __syncthreads();                                                        \
        if (c + 3 < NCHUNK) load_stage((c + 3) & 3, c + 3);                     \
        CP_COMMIT();                                                            \
        const uint32_t base = sb + st * STG;                                    \
        _Pragma("unroll")                                                       \
        for (int ks = 0; ks < 4; ++ks) {                                        \
            const int kc0 = ks * 2;                                             \
            uint32_t ah[4][4], bh[3][4];                                        \
            _Pragma("unroll")                                                   \
            for (int mf = 0; mf < 4; ++mf)                                      \
                ldsm4(ah[mf], base + (a_row_base + mf * 16) * ROWB              \
                                  + (a_kc + kc0) * 16);                         \
            _Pragma("unroll")                                                   \
            for (int nf = 0; nf < 3; ++nf)                                      \
                ldsm4(bh[nf], base + MATSZ_A + (b_row_base + nf * 16) * ROWB    \
                                  + (b_kc + kc0) * 16);                         \
            _Pragma("unroll")                                                   \
            for (int mf = 0; mf < 4; ++mf)                                      \
                _Pragma("unroll")                                               \
                for (int nf = 0; nf < 3; ++nf) {                                \
                    mma16816(acc[mf][nf * 2],     ah[mf], &bh[nf][0]);          \
                    mma16816(acc[mf][nf * 2 + 1], ah[mf], &bh[nf][2]);          \
                }                                                               \
        }                                                                       \
    }

// ============== 6a. GEMM1  Y1 = S @ X  -> Y1h + fused B1h transpose =========
__global__ __launch_bounds__(256, 1) void k_mma1() {
    extern __shared__ char smem[];
    const uint32_t sb = smem_u32(smem);
    const int tid = threadIdx.x;
    const int lane = tid & 31;
    const int warp = tid >> 5;
    const int m_off = (warp & 1) * 64;
    const int n_off = (warp >> 1) * 48;

    GEMM_BODY(g_B0h)

    __syncthreads();
    // g_Y1h [row][col]
#pragma unroll
    for (int mf = 0; mf < 4; ++mf) {
#pragma unroll
        for (int half = 0; half < 2; ++half) {
            int rowL = m_off + mf * 16 + half * 8 + (lane >> 2);
            __half* yr = g_Y1h + (size_t)(m0 + rowL) * BIS + c0;
#pragma unroll
            for (int n8 = 0; n8 < 6; ++n8) {
                int colL = n_off + n8 * 8 + (lane & 3) * 2;
                __half h0 = __float2half_rn(acc[mf][n8][half * 2]);
                __half h1 = __float2half_rn(acc[mf][n8][half * 2 + 1]);
                *(__half2*)(yr + colL) = __halves2half2(h0, h1);
            }
        }
    }
    // two-pass smem transpose (96 cols each) -> g_B1h [col][row]
    __half* sh = (__half*)smem;
#pragma unroll
    for (int p = 0; p < 2; ++p) {
        __syncthreads();
        if (n_off >= p * 96 && n_off < p * 96 + 96) {
#pragma unroll
            for (int mf = 0; mf < 4; ++mf) {
#pragma unroll
                for (int half = 0; half < 2; ++half) {
                    int rowL = m_off + mf * 16 + half * 8 + (lane >> 2);
#pragma unroll
                    for (int n8 = 0; n8 < 6; ++n8) {
                        int colL = n_off + n8 * 8 + (lane & 3) * 2 - p * 96;
                        sh[colL * ROWP + rowL] =
                            __float2half_rn(acc[mf][n8][half * 2]);
                        sh[(colL + 1) * ROWP + rowL] =
                            __float2half_rn(acc[mf][n8][half * 2 + 1]);
                    }
                }
            }
        }
        __syncthreads();
        int col = tid >> 1, rh = tid & 1;
        if (col < 96) {
            const __half* srow = sh + col * ROWP + rh * 64;
            __half* drow = g_B1h + (size_t)(c0 + p * 96 + col) * NN + m0 + rh * 64;
#pragma unroll
            for (int q = 0; q < 16; ++q)
                *(uint2*)(drow + q * 4) = *(const uint2*)(srow + q * 4);
        }
    }
}

// ============== 6b. GEMM2  Y2 = S @ Y1  -> Y2h ==============================
__global__ __launch_bounds__(256, 1) void k_mma2() {
    extern __shared__ char smem[];
    const uint32_t sb = smem_u32(smem);
    const int tid = threadIdx.x;
    const int lane = tid & 31;
    const int warp = tid >> 5;
    const int m_off = (warp & 1) * 64;
    const int n_off = (warp >> 1) * 48;

    GEMM_BODY(g_B1h)

#pragma unroll
    for (int mf = 0; mf < 4; ++mf) {
#pragma unroll
        for (int half = 0; half < 2; ++half) {
            int rowL = m_off + mf * 16 + half * 8 + (lane >> 2);
            __half* yr = g_Y2h + (size_t)(m0 + rowL) * BIS + c0;
#pragma unroll
            for (int n8 = 0; n8 < 6; ++n8) {
                int colL = n_off + n8 * 8 + (lane & 3) * 2;
                __half h0 = __float2half_rn(acc[mf][n8][half * 2]);
                __half h1 = __float2half_rn(acc[mf][n8][half * 2 + 1]);
                *(__half2*)(yr + colL) = __halves2half2(h0, h1);
            }
        }
    }
}

// ------- 7. per-node generated weights + bias (16 rows/block) ---------------
// es layout: [2][d][r] so e-vectors load as broadcast float4 (4 rows at once)
__global__ __launch_bounds__(256) void k_weights(const float* __restrict__ E1, const float* __restrict__ E2,
                          const float* __restrict__ Wp, const float* __restrict__ Wp2,
                          const float* __restrict__ bp, const float* __restrict__ bp2) {
    int n0 = blockIdx.x * 16, tid = threadIdx.x;
    __shared__ __align__(16) float e1s[EE][16];   // [d][r]
    __shared__ __align__(16) float e2s[EE][16];
    {
        int r = tid >> 4, d = tid & 15;
        e1s[d][r] = E1[(n0 + r) * EE + d];
        e2s[d][r] = E2[(n0 + r) * EE + d];
    }
    __syncthreads();

    for (int q = tid; q < PW; q += 256) {
        float acc[16];
#pragma unroll
        for (int r = 0; r < 16; ++r) acc[r] = 0.f;
#pragma unroll
        for (int d = 0; d < EE; ++d) {
            float w1 = Wp[(size_t)d * PW + q];
            float w2 = Wp2[(size_t)d * PW + q];
            const float* e1r = e1s[d];
            const float* e2r = e2s[d];
#pragma unroll
            for (int r = 0; r < 16; ++r)
                acc[r] = fmaf(e1r[r], w1, fmaf(e2r[r], w2, acc[r]));
        }
#pragma unroll
        for (int r = 0; r < 16; ++r)
            g_W[(size_t)(n0 + r) * PW + q] = acc[r];
    }

    // bias: 16 rows x 32 o
#pragma unroll
    for (int idx = tid; idx < 16 * OO; idx += 256) {
        int r = idx >> 5, o = idx & 31;
        float a = 0.f;
#pragma unroll
        for (int d = 0; d < EE; ++d)
            a = fmaf(e1s[d][r], bp[d * OO + o], fmaf(e2s[d][r], bp2[d * OO + o], a));
        g_bias[(n0 + r) * OO + o] = a;
    }
}

// -------- 8. gconv (f32x2 packed FMA; hop0 x fp32; hops 1,2 fp16) -----------
__global__ __launch_bounds__(384) void k_gconv(const float* __restrict__ x,
                                               float* __restrict__ out) {
    int n = blockIdx.x, tid = threadIdx.x;
    __shared__ __align__(16) float Ws[PW];
    __shared__ float bsh[OO];
    for (int q = tid; q < PW; q += 384) Ws[q] = g_W[(size_t)n * PW + q];
    if (tid < OO) bsh[tid] = g_bias[n * OO + tid];
    __syncthreads();
    int b = tid / SS, s = tid - b * SS;
    unsigned long long acc2[OO / 2];
#pragma unroll
    for (int j = 0; j < OO / 2; ++j) acc2[j] = pk2(bsh[2 * j], bsh[2 * j + 1]);

    // hop 0: x[b,i,n,s] fp32
    {
        const float* yb = x + ((size_t)(b * II) * NN + n) * SS + s;
#pragma unroll 4
        for (int i = 0; i < II; ++i) {
            float v = yb[(size_t)i * NN * SS];
            unsigned long long v2 = pk2(v, v);
            const unsigned long long* wr2 = (const unsigned long long*)(Ws + i * OO);
#pragma unroll
            for (int j = 0; j < OO / 2; ++j) ffma2(acc2[j], v2, wr2[j]);
        }
    }
    // hops 1,2: Y1h, Y2h [n][(b,i,s)] fp16
    const __half* Yb[2] = { g_Y1h, g_Y2h };
#pragma unroll
    for (int k = 0; k < 2; ++k) {
        const __half* yb = Yb[k] + (size_t)n * BIS + (size_t)b * II * SS + s;
        const float* wk = Ws + (k + 1) * II * OO;
#pragma unroll 4
        for (int i = 0; i < II; ++i) {
            float v = __half2float(yb[i * SS]);
            unsigned long long v2 = pk2(v, v);
            const unsigned long long* wr2 = (const unsigned long long*)(wk + i * OO);
#pragma unroll
            for (int j = 0; j < OO / 2; ++j) ffma2(acc2[j], v2, wr2[j]);
        }
    }
#pragma unroll
    for (int j = 0; j < OO / 2; ++j) {
        float lo, hi;
        upk2(lo, hi, acc2[j]);
        out[(((size_t)b * OO + 2 * j) * NN + n) * SS + s] = lo;
        out[(((size_t)b * OO + 2 * j + 1) * NN + n) * SS + s] = hi;
    }
}

// ---------------------------------------------------------------------------
extern "C" void kernel_launch(void* const* d_in, const int* in_sizes, int n_in,
                              void* d_out, int out_size) {
    const float* x    = (const float*)d_in[0];
    const float* E1   = (const float*)d_in[1];
    const float* E2   = (const float*)d_in[2];
    const float* Wp   = (const float*)d_in[3];
    const float* Wp2  = (const float*)d_in[4];
    const float* bp   = (const float*)d_in[5];
    const float* bp2  = (const float*)d_in[6];
    const float* fc0w = (const float*)d_in[7];
    const float* fc0b = (const float*)d_in[8];
    const float* fc1w = (const float*)d_in[9];
    const float* fc1b = (const float*)d_in[10];
    const float* fc2w = (const float*)d_in[11];
    const float* fc2b = (const float*)d_in[12];
    float* out = (float*)d_out;

    cudaFuncSetAttribute(k_mma1, cudaFuncAttributeMaxDynamicSharedMemorySize, SMTOT);
    cudaFuncSetAttribute(k_mma2, cudaFuncAttributeMaxDynamicSharedMemorySize, SMTOT);
    cudaFuncSetAttribute(k_adj,  cudaFuncAttributeMaxDynamicSharedMemorySize, ADJ_SMEM);

    k_h1<<<II * NN / 256, 256>>>(x, fc0w, fc0b);
    k_h2<<<II * EE, 256>>>(fc1w, fc1b);
    k_m<<<1, 256>>>(fc2w, fc2b);
    k_adj<<<NN / 16, 256, ADJ_SMEM>>>(E1, E2);

    k_split0<<<dim3(BB * II, NN / 256), 256>>>(x);     // x -> B0h

    dim3 gg(NN / 128, BIS / 192);
    k_mma1<<<gg, 256, SMTOT>>>();                      // Y1h + B1h (fused)
    k_mma2<<<gg, 256, SMTOT>>>();                      // Y2h

    k_weights<<<NN / 16, 256>>>(E1, E2, Wp, Wp2, bp, bp2);
    k_gconv<<<NN, 384>>>(x, out);
}

// round 16
// speedup vs baseline: 1.0358x; 1.0358x over previous
#include <cuda_runtime.h>
#include <cuda_fp16.h>
#include <cstdint>

#define NN   2048
#define BB   32
#define II   32
#define OO   32
#define SS   12
#define EE   16
#define KK   3          // K+1 hops
#define BIS  12288      // B*II*SS
#define PW   (KK*II*OO)

// ---------------- scratch (device globals) ----------------------------------
__device__ float g_h1[II * NN];
__device__ float g_h2[II * EE];
__device__ float g_m[EE * EE];
__device__ float g_W[(size_t)NN * PW];
__device__ float g_bias[NN * OO];
// fp16 operands / results
__device__ __align__(16) __half g_Ah[(size_t)NN * NN];    // S        [n][k]
__device__ __align__(16) __half g_B0h[(size_t)BIS * NN];  // X^T      [col][k]
__device__ __align__(16) __half g_B1h[(size_t)BIS * NN];  // Y1^T     [col][k]
__device__ __align__(16) __half g_Y1h[(size_t)NN * BIS];  // Y1       [n][col]
__device__ __align__(16) __half g_Y2h[(size_t)NN * BIS];  // Y2       [n][col]

// ---------------- helpers ----------------------------------------------------
__device__ __forceinline__ uint32_t smem_u32(const void* p) {
    uint32_t a;
    asm("{ .reg .u64 t; cvta.to.shared.u64 t, %1; cvt.u32.u64 %0, t; }" : "=r"(a) : "l"(p));
    return a;
}
__device__ __forceinline__ void cp16(uint32_t dst, const void* src) {
    asm volatile("cp.async.cg.shared.global [%0], [%1], 16;" :: "r"(dst), "l"(src) : "memory");
}
#define CP_COMMIT() asm volatile("cp.async.commit_group;" ::: "memory")
#define CP_WAIT2()  asm volatile("cp.async.wait_group 2;" ::: "memory")
#define CP_WAIT0()  asm volatile("cp.async.wait_group 0;" ::: "memory")

__device__ __forceinline__ void ldsm4(uint32_t* r, uint32_t addr) {
    asm volatile("ldmatrix.sync.aligned.m8n8.x4.shared.b16 {%0,%1,%2,%3}, [%4];"
                 : "=r"(r[0]), "=r"(r[1]), "=r"(r[2]), "=r"(r[3]) : "r"(addr));
}
__device__ __forceinline__ void mma16816(float* c, const uint32_t* a, const uint32_t* b) {
    asm volatile(
        "mma.sync.aligned.m16n8k16.row.col.f32.f16.f16.f32 "
        "{%0,%1,%2,%3}, {%4,%5,%6,%7}, {%8,%9}, {%0,%1,%2,%3};"
        : "+f"(c[0]), "+f"(c[1]), "+f"(c[2]), "+f"(c[3])
        : "r"(a[0]), "r"(a[1]), "r"(a[2]), "r"(a[3]), "r"(b[0]), "r"(b[1]));
}
// packed fp32x2 FMA (base Blackwell PTX; per-lane IEEE fma)
__device__ __forceinline__ void ffma2(unsigned long long& c,
                                      unsigned long long a, unsigned long long b) {
    asm("fma.rn.f32x2 %0, %1, %2, %0;" : "+l"(c) : "l"(a), "l"(b));
}
__device__ __forceinline__ unsigned long long pk2(float lo, float hi) {
    unsigned long long r;
    asm("mov.b64 %0, {%1, %2};" : "=l"(r) : "f"(lo), "f"(hi));
    return r;
}
__device__ __forceinline__ void upk2(float& lo, float& hi, unsigned long long v) {
    asm("mov.b64 {%0, %1}, %2;" : "=f"(lo), "=f"(hi) : "l"(v));
}

// ---------------- 1. h1 -----------------------------------------------------
__global__ void k_h1(const float* __restrict__ x,
                     const float* __restrict__ fc0w,
                     const float* __restrict__ fc0b) {
    int idx = blockIdx.x * 256 + threadIdx.x;
    float acc = fc0b[0];
    const float* xr = x + (size_t)idx * SS;
#pragma unroll
    for (int s = 0; s < SS; ++s) acc = fmaf(xr[s], fc0w[s], acc);
    g_h1[idx] = tanhf(acc);
}

// ---------------- 2. h2 -----------------------------------------------------
__global__ void k_h2(const float* __restrict__ fc1w,
                     const float* __restrict__ fc1b) {
    int i = blockIdx.x >> 4;
    int d = blockIdx.x & 15;
    int tid = threadIdx.x;
    float p = 0.f;
    for (int n = tid; n < NN; n += 256)
        p = fmaf(g_h1[i * NN + n], fc1w[d * NN + n], p);
    __shared__ float red[256];
    red[tid] = p; __syncthreads();
    for (int st = 128; st > 0; st >>= 1) {
        if (tid < st) red[tid] += red[tid + st];
        __syncthreads();
    }
    if (tid == 0) g_h2[i * EE + d] = tanhf(red[0] + fc1b[d]);
}

// ---------------- 3. m ------------------------------------------------------
__global__ void k_m(const float* __restrict__ fc2w,
                    const float* __restrict__ fc2b) {
    int t = threadIdx.x;
    int d = t >> 4, e = t & 15;
    float acc = fc2b[e];
#pragma unroll
    for (int i = 0; i < II; ++i) acc = fmaf(g_h2[i * EE + d], fc2w[e * II + i], acc);
    g_m[d * EE + e] = tanhf(acc);
}

// ------- 4. adjacency softmax -> fp16 (16 rows/block, E2 tiled in smem) -----
// dyn smem: buf[16][NN] | E2s[256][17] | p[16][16]
#define ADJ_TS 256
#define ADJ_SMEM ((16 * NN + ADJ_TS * 17 + 256) * 4)
__global__ __launch_bounds__(256) void k_adj(const float* __restrict__ E1,
                                             const float* __restrict__ E2) {
    extern __shared__ float asmem[];
    float* buf = asmem;                        // 16*NN
    float* E2s = asmem + 16 * NN;              // 256*17
    float* p   = E2s + ADJ_TS * 17;            // 16*16
    int tid = threadIdx.x;
    int n0 = blockIdx.x * 16;

    {
        int r = tid >> 4, e = tid & 15;
        float a = 0.f;
#pragma unroll
        for (int d = 0; d < EE; ++d)
            a = fmaf(E1[(n0 + r) * EE + d], g_m[d * EE + e], a);
        p[tid] = a;
    }
    __syncthreads();
    const int r = tid >> 4, mloc = tid & 15;
    float pl[EE];
#pragma unroll
    for (int e = 0; e < EE; ++e) pl[e] = p[r * 16 + e];

    float lmax = 0.f;   // relu => logits >= 0
    for (int mt = 0; mt < NN; mt += ADJ_TS) {
        __syncthreads();
#pragma unroll
        for (int j = 0; j < 16; ++j) {
            int idx = tid + j * 256;          // 4096 scalars
            int mc = idx >> 4, e = idx & 15;
            E2s[mc * 17 + e] = E2[(size_t)(mt + mc) * EE + e];
        }
        __syncthreads();
#pragma unroll
        for (int j = 0; j < ADJ_TS / 16; ++j) {
            int mc = mloc + j * 16;
            const float* er = E2s + mc * 17;
            float a = 0.f;
#pragma unroll
            for (int e = 0; e < EE; ++e) a = fmaf(pl[e], er[e], a);
            a = fmaxf(a, 0.f);
            buf[r * NN + mt + mc] = a;
            lmax = fmaxf(lmax, a);
        }
    }
#pragma unroll
    for (int o = 8; o; o >>= 1) lmax = fmaxf(lmax, __shfl_xor_sync(0xffffffffu, lmax, o));

    float lsum = 0.f;
#pragma unroll
    for (int j = 0; j < NN / 16; ++j) {
        int mc = mloc + j * 16;
        float v = __expf(buf[r * NN + mc] - lmax);
        buf[r * NN + mc] = v;
        lsum += v;
    }
#pragma unroll
    for (int o = 8; o; o >>= 1) lsum += __shfl_xor_sync(0xffffffffu, lsum, o);
    float inv = 1.0f / lsum;

#pragma unroll
    for (int j = 0; j < NN / 16; ++j) {
        int mc = mloc + j * 16;
        g_Ah[(size_t)(n0 + r) * NN + mc] = __float2half_rn(buf[r * NN + mc] * inv);
    }
}

// --------- 5. B0h = fp16(x^T):  B0[(b,i,s)][m] = x[b,i,m,s] ----------------
__global__ __launch_bounds__(256) void k_split0(const float* __restrict__ x) {
    int bi = blockIdx.x;
    int m = blockIdx.y * 256 + threadIdx.x;
    const float* src = x + ((size_t)bi * NN + m) * SS;
    float v[SS];
#pragma unroll
    for (int s = 0; s < SS; ++s) v[s] = src[s];
#pragma unroll
    for (int s = 0; s < SS; ++s)
        g_B0h[(size_t)(bi * SS + s) * NN + m] = __float2half_rn(v[s]);
}

// ============== GEMM core defs ==============================================
// BM=128, BN=192, BK=64; warp tile 64x48 (8 warps = 2m x 4n); grid 16x64=1024
#define ROWB 144
#define MATSZ_A (128 * ROWB)    // 18432
#define MATSZ_B (192 * ROWB)    // 27648
#define STG   (MATSZ_A + MATSZ_B)   // 46080
#define NSTG  4
#define SMTOT (NSTG * STG)      // 184320
#define NCHUNK (NN / 64)        // 32
#define ROWP 132                // fp16 transpose-staging row pitch

// common GEMM body: computes acc for one 128x192 tile of C = Ah @ B^T
#define GEMM_BODY(pB)                                                           \
    const char* pAh = (const char*)g_Ah;                                        \
    const char* pBh = (const char*)(pB);                                        \
    const int m0 = blockIdx.x * 128;                                            \
    const int c0 = blockIdx.y * 192;                                            \
    auto load_stage = [&](int stg, int chunk) {                                 \
        const uint32_t base = sb + stg * STG;                                   \
        const int k0 = chunk * 64;                                              \
        _Pragma("unroll")                                                       \
        for (int r = 0; r < 10; ++r) {                                          \
            int id = tid + r * 256;                                             \
            if (id < 1024) {                                                    \
                int row = id >> 3, cc = id & 7;                                 \
                cp16(base + row * ROWB + cc * 16,                               \
                     pAh + ((size_t)(m0 + row) * NN + k0 + cc * 8) * 2);        \
            } else {                                                            \
                int idx = id - 1024;                                            \
                int row = idx >> 3, cc = idx & 7;                               \
                cp16(base + MATSZ_A + row * ROWB + cc * 16,                     \
                     pBh + ((size_t)(c0 + row) * NN + k0 + cc * 8) * 2);        \
            }                                                                   \
        }                                                                       \
    };                                                                          \
    float acc[4][6][4];                                                         \
    _Pragma("unroll")                                                           \
    for (int i = 0; i < 4; ++i)                                                 \
        _Pragma("unroll")                                                       \
        for (int j = 0; j < 6; ++j)                                             \
            _Pragma("unroll")                                                   \
            for (int q = 0; q < 4; ++q) acc[i][j][q] = 0.f;                     \
    load_stage(0, 0); CP_COMMIT();                                              \
    load_stage(1, 1); CP_COMMIT();                                              \
    load_stage(2, 2); CP_COMMIT();                                              \
    const int grp = lane >> 3, lr = lane & 7;                                   \
    const int a_row_base = m_off + (grp & 1) * 8 + lr;                          \
    const int a_kc = grp >> 1;                                                  \
    const int b_row_base = n_off + (grp >> 1) * 8 + lr;                         \
    const int b_kc = grp & 1;                                                   \
    for (int c = 0; c < NCHUNK; ++c) {                                          \
        const int st = c & 3;                                                   \
        if (c + 1 < NCHUNK) CP_WAIT2(); else CP_WAIT0();                        \
        __syncthreads();                                                        \
        if (c + 3 < NCHUNK) load_stage((c + 3) & 3, c + 3);                     \
        CP_COMMIT();                                                            \
        const uint32_t base = sb + st * STG;                                    \
        _Pragma("unroll")                                                       \
        for (int ks = 0; ks < 4; ++ks) {                                        \
            const int kc0 = ks * 2;                                             \
            uint32_t ah[4][4], bh[3][4];                                        \
            _Pragma("unroll")                                                   \
            for (int mf = 0; mf < 4; ++mf)                                      \
                ldsm4(ah[mf], base + (a_row_base + mf * 16) * ROWB              \
                                  + (a_kc + kc0) * 16);                         \
            _Pragma("unroll")                                                   \
            for (int nf = 0; nf < 3; ++nf)                                      \
                ldsm4(bh[nf], base + MATSZ_A + (b_row_base + nf * 16) * ROWB    \
                                  + (b_kc + kc0) * 16);                         \
            _Pragma("unroll")                                                   \
            for (int mf = 0; mf < 4; ++mf)                                      \
                _Pragma("unroll")                                               \
                for (int nf = 0; nf < 3; ++nf) {                                \
                    mma16816(acc[mf][nf * 2],     ah[mf], &bh[nf][0]);          \
                    mma16816(acc[mf][nf * 2 + 1], ah[mf], &bh[nf][2]);          \
                }                                                               \
        }                                                                       \
    }

// ============== 6a. GEMM1  Y1 = S @ X  -> Y1h + fused B1h transpose =========
__global__ __launch_bounds__(256, 1) void k_mma1() {
    extern __shared__ char smem[];
    const uint32_t sb = smem_u32(smem);
    const int tid = threadIdx.x;
    const int lane = tid & 31;
    const int warp = tid >> 5;
    const int m_off = (warp & 1) * 64;
    const int n_off = (warp >> 1) * 48;

    GEMM_BODY(g_B0h)

    __syncthreads();
    // g_Y1h [row][col]
#pragma unroll
    for (int mf = 0; mf < 4; ++mf) {
#pragma unroll
        for (int half = 0; half < 2; ++half) {
            int rowL = m_off + mf * 16 + half * 8 + (lane >> 2);
            __half* yr = g_Y1h + (size_t)(m0 + rowL) * BIS + c0;
#pragma unroll
            for (int n8 = 0; n8 < 6; ++n8) {
                int colL = n_off + n8 * 8 + (lane & 3) * 2;
                __half h0 = __float2half_rn(acc[mf][n8][half * 2]);
                __half h1 = __float2half_rn(acc[mf][n8][half * 2 + 1]);
                *(__half2*)(yr + colL) = __halves2half2(h0, h1);
            }
        }
    }
    // two-pass smem transpose (96 cols each) -> g_B1h [col][row]
    __half* sh = (__half*)smem;
#pragma unroll
    for (int p = 0; p < 2; ++p) {
        __syncthreads();
        if (n_off >= p * 96 && n_off < p * 96 + 96) {
#pragma unroll
            for (int mf = 0; mf < 4; ++mf) {
#pragma unroll
                for (int half = 0; half < 2; ++half) {
                    int rowL = m_off + mf * 16 + half * 8 + (lane >> 2);
#pragma unroll
                    for (int n8 = 0; n8 < 6; ++n8) {
                        int colL = n_off + n8 * 8 + (lane & 3) * 2 - p * 96;
                        sh[colL * ROWP + rowL] =
                            __float2half_rn(acc[mf][n8][half * 2]);
                        sh[(colL + 1) * ROWP + rowL] =
                            __float2half_rn(acc[mf][n8][half * 2 + 1]);
                    }
                }
            }
        }
        __syncthreads();
        int col = tid >> 1, rh = tid & 1;
        if (col < 96) {
            const __half* srow = sh + col * ROWP + rh * 64;
            __half* drow = g_B1h + (size_t)(c0 + p * 96 + col) * NN + m0 + rh * 64;
#pragma unroll
            for (int q = 0; q < 16; ++q)
                *(uint2*)(drow + q * 4) = *(const uint2*)(srow + q * 4);
        }
    }
}

// ============== 6b. GEMM2  Y2 = S @ Y1  -> Y2h ==============================
__global__ __launch_bounds__(256, 1) void k_mma2() {
    extern __shared__ char smem[];
    const uint32_t sb = smem_u32(smem);
    const int tid = threadIdx.x;
    const int lane = tid & 31;
    const int warp = tid >> 5;
    const int m_off = (warp & 1) * 64;
    const int n_off = (warp >> 1) * 48;

    GEMM_BODY(g_B1h)

#pragma unroll
    for (int mf = 0; mf < 4; ++mf) {
#pragma unroll
        for (int half = 0; half < 2; ++half) {
            int rowL = m_off + mf * 16 + half * 8 + (lane >> 2);
            __half* yr = g_Y2h + (size_t)(m0 + rowL) * BIS + c0;
#pragma unroll
            for (int n8 = 0; n8 < 6; ++n8) {
                int colL = n_off + n8 * 8 + (lane & 3) * 2;
                __half h0 = __float2half_rn(acc[mf][n8][half * 2]);
                __half h1 = __float2half_rn(acc[mf][n8][half * 2 + 1]);
                *(__half2*)(yr + colL) = __halves2half2(h0, h1);
            }
        }
    }
}

// ---------------- 7. per-node generated weights + bias (R14 version) --------
__global__ void k_weights(const float* __restrict__ E1, const float* __restrict__ E2,
                          const float* __restrict__ Wp, const float* __restrict__ Wp2,
                          const float* __restrict__ bp, const float* __restrict__ bp2) {
    int n = blockIdx.x, tid = threadIdx.x;
    __shared__ float e1[EE], e2[EE];
    if (tid < EE) e1[tid] = E1[n * EE + tid];
    else if (tid < 2 * EE) e2[tid - EE] = E2[n * EE + tid - EE];
    __syncthreads();
    float l1[EE], l2[EE];
#pragma unroll
    for (int d = 0; d < EE; ++d) { l1[d] = e1[d]; l2[d] = e2[d]; }
    for (int q = tid; q < PW; q += 256) {
        float acc = 0.f;
#pragma unroll
        for (int d = 0; d < EE; ++d)
            acc = fmaf(l1[d], Wp[d * PW + q], fmaf(l2[d], Wp2[d * PW + q], acc));
        g_W[(size_t)n * PW + q] = acc;
    }
    if (tid < OO) {
        float acc = 0.f;
#pragma unroll
        for (int d = 0; d < EE; ++d)
            acc = fmaf(l1[d], bp[d * OO + tid], fmaf(l2[d], bp2[d * OO + tid], acc));
        g_bias[n * OO + tid] = acc;
    }
}

// -------- 8. gconv (f32x2 packed FMA; hop0 x fp32; hops 1,2 fp16) -----------
__global__ __launch_bounds__(384) void k_gconv(const float* __restrict__ x,
                                               float* __restrict__ out) {
    int n = blockIdx.x, tid = threadIdx.x;
    __shared__ __align__(16) float Ws[PW];
    __shared__ float bsh[OO];
    for (int q = tid; q < PW; q += 384) Ws[q] = g_W[(size_t)n * PW + q];
    if (tid < OO) bsh[tid] = g_bias[n * OO + tid];
    __syncthreads();
    int b = tid / SS, s = tid - b * SS;
    unsigned long long acc2[OO / 2];
#pragma unroll
    for (int j = 0; j < OO / 2; ++j) acc2[j] = pk2(bsh[2 * j], bsh[2 * j + 1]);

    // hop 0: x[b,i,n,s] fp32
    {
        const float* yb = x + ((size_t)(b * II) * NN + n) * SS + s;
#pragma unroll 4
        for (int i = 0; i < II; ++i) {
            float v = yb[(size_t)i * NN * SS];
            unsigned long long v2 = pk2(v, v);
            const unsigned long long* wr2 = (const unsigned long long*)(Ws + i * OO);
#pragma unroll
            for (int j = 0; j < OO / 2; ++j) ffma2(acc2[j], v2, wr2[j]);
        }
    }
    // hops 1,2: Y1h, Y2h [n][(b,i,s)] fp16
    const __half* Yb[2] = { g_Y1h, g_Y2h };
#pragma unroll
    for (int k = 0; k < 2; ++k) {
        const __half* yb = Yb[k] + (size_t)n * BIS + (size_t)b * II * SS + s;
        const float* wk = Ws + (k + 1) * II * OO;
#pragma unroll 4
        for (int i = 0; i < II; ++i) {
            float v = __half2float(yb[i * SS]);
            unsigned long long v2 = pk2(v, v);
            const unsigned long long* wr2 = (const unsigned long long*)(wk + i * OO);
#pragma unroll
            for (int j = 0; j < OO / 2; ++j) ffma2(acc2[j], v2, wr2[j]);
        }
    }
#pragma unroll
    for (int j = 0; j < OO / 2; ++j) {
        float lo, hi;
        upk2(lo, hi, acc2[j]);
        out[(((size_t)b * OO + 2 * j) * NN + n) * SS + s] = lo;
        out[(((size_t)b * OO + 2 * j + 1) * NN + n) * SS + s] = hi;
    }
}

// ---------------------------------------------------------------------------
extern "C" void kernel_launch(void* const* d_in, const int* in_sizes, int n_in,
                              void* d_out, int out_size) {
    const float* x    = (const float*)d_in[0];
    const float* E1   = (const float*)d_in[1];
    const float* E2   = (const float*)d_in[2];
    const float* Wp   = (const float*)d_in[3];
    const float* Wp2  = (const float*)d_in[4];
    const float* bp   = (const float*)d_in[5];
    const float* bp2  = (const float*)d_in[6];
    const float* fc0w = (const float*)d_in[7];
    const float* fc0b = (const float*)d_in[8];
    const float* fc1w = (const float*)d_in[9];
    const float* fc1b = (const float*)d_in[10];
    const float* fc2w = (const float*)d_in[11];
    const float* fc2b = (const float*)d_in[12];
    float* out = (float*)d_out;

    cudaFuncSetAttribute(k_mma1, cudaFuncAttributeMaxDynamicSharedMemorySize, SMTOT);
    cudaFuncSetAttribute(k_mma2, cudaFuncAttributeMaxDynamicSharedMemorySize, SMTOT);
    cudaFuncSetAttribute(k_adj,  cudaFuncAttributeMaxDynamicSharedMemorySize, ADJ_SMEM);

    k_h1<<<II * NN / 256, 256>>>(x, fc0w, fc0b);
    k_h2<<<II * EE, 256>>>(fc1w, fc1b);
    k_m<<<1, 256>>>(fc2w, fc2b);
    k_adj<<<NN / 16, 256, ADJ_SMEM>>>(E1, E2);

    k_split0<<<dim3(BB * II, NN / 256), 256>>>(x);     // x -> B0h

    dim3 gg(NN / 128, BIS / 192);
    k_mma1<<<gg, 256, SMTOT>>>();                      // Y1h + B1h (fused)
    k_mma2<<<gg, 256, SMTOT>>>();                      // Y2h

    k_weights<<<NN, 256>>>(E1, E2, Wp, Wp2, bp, bp2);
    k_gconv<<<NN, 384>>>(x, out);
}